// round 3
// baseline (speedup 1.0000x reference)
#include <cuda_runtime.h>

#define NMAX 100000
#define EPS 1e-5f

typedef unsigned long long ull;

// ---------------- scratch ----------------
__device__ float g_buf_h[(size_t)NMAX * 64];   // h_raw (ReLU output, pre-BN)
__device__ float g_buf_m[(size_t)NMAX * 32];   // m_raw (pre-BN)
__device__ float g_agg  [(size_t)NMAX * 32];   // segment-sum of BN(m)
__device__ float g_buf_u[(size_t)NMAX * 64];   // u_raw
// [0:64) sum_h [64:128) sq_h [128:160) sum_m [192:224) sq_m [256:320) sum_u [320:384) sq_u
__device__ float g_stats[384];

// ---------------- f32x2 helpers ----------------
__device__ __forceinline__ void ffma2(ull &d, ull a, ull b) {
    asm("fma.rn.f32x2 %0, %1, %2, %0;" : "+l"(d) : "l"(a), "l"(b));
}
__device__ __forceinline__ ull dup2(float w) {
    ull r; unsigned u = __float_as_uint(w);
    asm("mov.b64 %0, {%1, %1};" : "=l"(r) : "r"(u)); return r;
}
__device__ __forceinline__ float2 unp2(ull v) {
    unsigned lo, hi;
    asm("mov.b64 {%0, %1}, %2;" : "=r"(lo), "=r"(hi) : "l"(v));
    return make_float2(__uint_as_float(lo), __uint_as_float(hi));
}
__device__ __forceinline__ ull ldd(const float2* p) {
    return *reinterpret_cast<const ull*>(p);
}

// ================= K1: zero agg; h_raw = ReLU(nodes @ W_in + b); h stats ===========
// tile 128 nodes/block; warp = 16 nodes (8 pairs) x 64 ch (lane c, c+32)
__global__ __launch_bounds__(256) void k1_input(
    const float* __restrict__ nodes, const float* __restrict__ W,
    const float* __restrict__ b, int Nn, int zeroN4)
{
    __shared__ float2 sWd[32 * 64];        // 16 KB, dup'd weights [k][c]
    __shared__ ulonglong2 sX[64 * 17];     // 64 pair rows, stride 17 ull2 (16 used)
    __shared__ float rs[64], rq[64];
    int tid = threadIdx.x;
    float4 z4 = make_float4(0.f, 0.f, 0.f, 0.f);
    // zero agg slice (visible to k3 via kernel ordering)
    for (int i = blockIdx.x * 256 + tid; i < zeroN4; i += gridDim.x * 256)
        reinterpret_cast<float4*>(g_agg)[i] = z4;
    for (int i = tid; i < 2048; i += 256) { float w = W[i]; sWd[i] = make_float2(w, w); }
    if (tid < 64) { rs[tid] = 0.f; rq[tid] = 0.f; }
    int c = tid & 31, wp = tid >> 5;
    ull bl = dup2(b[c]), bh = dup2(b[c + 32]);
    float s0 = 0.f, q0 = 0.f, s1 = 0.f, q1 = 0.f;
    float* sXf = (float*)sX;
    const float4* np = (const float4*)nodes;

    for (int tile = blockIdx.x * 128; tile < Nn; tile += gridDim.x * 128) {
        __syncthreads();
        for (int i4 = tid; i4 < 1024; i4 += 256) {
            int n = i4 >> 3, j = i4 & 7, k0 = j * 4;
            int gn = tile + n;
            float4 v = (gn < Nn) ? np[(size_t)gn * 8 + j] : z4;
            float* dst = sXf + (n >> 1) * 68 + (n & 1);
            dst[(k0 + 0) * 2] = v.x; dst[(k0 + 1) * 2] = v.y;
            dst[(k0 + 2) * 2] = v.z; dst[(k0 + 3) * 2] = v.w;
        }
        __syncthreads();

        ull a0[8], a1[8];
        #pragma unroll
        for (int p = 0; p < 8; p++) { a0[p] = bl; a1[p] = bh; }
        #pragma unroll
        for (int k2 = 0; k2 < 16; k2++) {
            int k = k2 * 2;
            ull w0 = ldd(&sWd[k * 64 + c]),        w1 = ldd(&sWd[k * 64 + c + 32]);
            ull w2 = ldd(&sWd[(k + 1) * 64 + c]),  w3 = ldd(&sWd[(k + 1) * 64 + c + 32]);
            #pragma unroll
            for (int p = 0; p < 8; p++) {
                ulonglong2 x = sX[(wp * 8 + p) * 17 + k2];
                ffma2(a0[p], x.x, w0); ffma2(a1[p], x.x, w1);
                ffma2(a0[p], x.y, w2); ffma2(a1[p], x.y, w3);
            }
        }
        #pragma unroll
        for (int p = 0; p < 8; p++) {
            float2 f0 = unp2(a0[p]), f1 = unp2(a1[p]);
            int n0 = tile + wp * 16 + 2 * p;
            float v;
            if (n0 < Nn) {
                v = fmaxf(f0.x, 0.f); g_buf_h[(size_t)n0 * 64 + c] = v;        s0 += v; q0 += v * v;
                v = fmaxf(f1.x, 0.f); g_buf_h[(size_t)n0 * 64 + c + 32] = v;   s1 += v; q1 += v * v;
            }
            if (n0 + 1 < Nn) {
                v = fmaxf(f0.y, 0.f); g_buf_h[(size_t)(n0 + 1) * 64 + c] = v;      s0 += v; q0 += v * v;
                v = fmaxf(f1.y, 0.f); g_buf_h[(size_t)(n0 + 1) * 64 + c + 32] = v; s1 += v; q1 += v * v;
            }
        }
    }
    __syncthreads();
    atomicAdd(&rs[c], s0);      atomicAdd(&rq[c], q0);
    atomicAdd(&rs[c + 32], s1); atomicAdd(&rq[c + 32], q1);
    __syncthreads();
    if (tid < 64) { atomicAdd(&g_stats[tid], rs[tid]); atomicAdd(&g_stats[64 + tid], rq[tid]); }
}

// ================= K2: m_raw = ReLU(BN(h) @ W_msg + b), BN folded =================
// tile 128 nodes; warp = 16 nodes (8 pairs) x 32 ch
__global__ __launch_bounds__(256) void k2_msg(
    const float* __restrict__ Wm, const float* __restrict__ bm,
    const float* __restrict__ gam, const float* __restrict__ bet,
    int Nn, float invN)
{
    __shared__ float2 sWd[64 * 32];        // 16 KB folded+dup'd [k][c]
    __shared__ ulonglong2 sH[64 * 33];     // 33.8 KB
    __shared__ float sSc[64], sSh[64], sB[32];
    __shared__ float rs[32], rq[32];
    int tid = threadIdx.x;
    if (tid < 64) {
        float mean = g_stats[tid] * invN;
        float var  = fmaf(-mean, mean, g_stats[64 + tid] * invN);
        float r = rsqrtf(var + EPS);
        float s = gam[tid] * r;
        sSc[tid] = s; sSh[tid] = bet[tid] - mean * s;
    }
    if (tid < 32) { sB[tid] = bm[tid]; rs[tid] = 0.f; rq[tid] = 0.f; }
    __syncthreads();
    for (int i = tid; i < 2048; i += 256) {
        float w = Wm[i] * sSc[i >> 5];
        sWd[i] = make_float2(w, w);
    }
    {
        int cc = tid & 31, part = tid >> 5;
        float acc = 0.f;
        #pragma unroll
        for (int j = part * 8; j < part * 8 + 8; j++) acc += sSh[j] * Wm[j * 32 + cc];
        atomicAdd(&sB[cc], acc);
    }
    __syncthreads();
    int c = tid & 31, wp = tid >> 5;
    ull bl = dup2(sB[c]);
    float s0 = 0.f, q0 = 0.f;
    float* sHf = (float*)sH;
    const float4* hp = (const float4*)g_buf_h;
    float4 z4 = make_float4(0.f, 0.f, 0.f, 0.f);

    for (int tile = blockIdx.x * 128; tile < Nn; tile += gridDim.x * 128) {
        __syncthreads();
        for (int i = tid; i < 2048; i += 256) {
            int n = i >> 4, j = i & 15, k0 = j * 4;
            int gn = tile + n;
            float4 v = (gn < Nn) ? hp[(size_t)gn * 16 + j] : z4;
            float* dst = sHf + (n >> 1) * 132 + (n & 1);
            dst[(k0 + 0) * 2] = v.x; dst[(k0 + 1) * 2] = v.y;
            dst[(k0 + 2) * 2] = v.z; dst[(k0 + 3) * 2] = v.w;
        }
        __syncthreads();

        ull a[8];
        #pragma unroll
        for (int p = 0; p < 8; p++) a[p] = bl;
        #pragma unroll 8
        for (int k2 = 0; k2 < 32; k2++) {
            int k = k2 * 2;
            ull w0 = ldd(&sWd[k * 32 + c]), w1 = ldd(&sWd[(k + 1) * 32 + c]);
            #pragma unroll
            for (int p = 0; p < 8; p++) {
                ulonglong2 x = sH[(wp * 8 + p) * 33 + k2];
                ffma2(a[p], x.x, w0); ffma2(a[p], x.y, w1);
            }
        }
        #pragma unroll
        for (int p = 0; p < 8; p++) {
            float2 f = unp2(a[p]);
            int n0 = tile + wp * 16 + 2 * p;
            if (n0 < Nn)     { float v = fmaxf(f.x, 0.f); g_buf_m[(size_t)n0 * 32 + c] = v;       s0 += v; q0 += v * v; }
            if (n0 + 1 < Nn) { float v = fmaxf(f.y, 0.f); g_buf_m[(size_t)(n0 + 1) * 32 + c] = v; s0 += v; q0 += v * v; }
        }
    }
    __syncthreads();
    atomicAdd(&rs[c], s0); atomicAdd(&rq[c], q0);
    __syncthreads();
    if (tid < 32) { atomicAdd(&g_stats[128 + tid], rs[tid]); atomicAdd(&g_stats[192 + tid], rq[tid]); }
}

// ================= K3: agg[dst] += BN(m_raw[src]); 4 edges / 8-thread group ========
__global__ __launch_bounds__(256) void k3_edges(
    const int* __restrict__ esrc, const int* __restrict__ edst,
    const float* __restrict__ gam, const float* __restrict__ bet,
    int E, float invN)
{
    __shared__ float sc[32], sh[32];
    if (threadIdx.x < 32) {
        int c = threadIdx.x;
        float mean = g_stats[128 + c] * invN;
        float var  = fmaf(-mean, mean, g_stats[192 + c] * invN);
        float r = rsqrtf(var + EPS);
        float s = gam[c] * r;
        sc[c] = s; sh[c] = bet[c] - mean * s;
    }
    __syncthreads();
    long long t = (long long)blockIdx.x * 256 + threadIdx.x;
    int g = (int)(t >> 3);
    int e0 = g * 4;
    if (e0 >= E) return;
    int j = (int)(t & 7);
    int c0 = j * 4;
    float scx = sc[c0], scy = sc[c0 + 1], scz = sc[c0 + 2], scw = sc[c0 + 3];
    float shx = sh[c0], shy = sh[c0 + 1], shz = sh[c0 + 2], shw = sh[c0 + 3];
    const float4* mp = (const float4*)g_buf_m;

    if (e0 + 4 <= E) {
        int4 s4 = *(const int4*)(esrc + e0);
        int4 d4 = *(const int4*)(edst + e0);
        float4 v0 = __ldg(mp + (size_t)s4.x * 8 + j);
        float4 v1 = __ldg(mp + (size_t)s4.y * 8 + j);
        float4 v2 = __ldg(mp + (size_t)s4.z * 8 + j);
        float4 v3 = __ldg(mp + (size_t)s4.w * 8 + j);
        float x, y, z, w; float* p;
        x = fmaf(v0.x, scx, shx); y = fmaf(v0.y, scy, shy); z = fmaf(v0.z, scz, shz); w = fmaf(v0.w, scw, shw);
        p = g_agg + (size_t)d4.x * 32 + c0;
        asm volatile("red.global.add.v4.f32 [%0], {%1,%2,%3,%4};" :: "l"(p), "f"(x), "f"(y), "f"(z), "f"(w) : "memory");
        x = fmaf(v1.x, scx, shx); y = fmaf(v1.y, scy, shy); z = fmaf(v1.z, scz, shz); w = fmaf(v1.w, scw, shw);
        p = g_agg + (size_t)d4.y * 32 + c0;
        asm volatile("red.global.add.v4.f32 [%0], {%1,%2,%3,%4};" :: "l"(p), "f"(x), "f"(y), "f"(z), "f"(w) : "memory");
        x = fmaf(v2.x, scx, shx); y = fmaf(v2.y, scy, shy); z = fmaf(v2.z, scz, shz); w = fmaf(v2.w, scw, shw);
        p = g_agg + (size_t)d4.z * 32 + c0;
        asm volatile("red.global.add.v4.f32 [%0], {%1,%2,%3,%4};" :: "l"(p), "f"(x), "f"(y), "f"(z), "f"(w) : "memory");
        x = fmaf(v3.x, scx, shx); y = fmaf(v3.y, scy, shy); z = fmaf(v3.z, scz, shz); w = fmaf(v3.w, scw, shw);
        p = g_agg + (size_t)d4.w * 32 + c0;
        asm volatile("red.global.add.v4.f32 [%0], {%1,%2,%3,%4};" :: "l"(p), "f"(x), "f"(y), "f"(z), "f"(w) : "memory");
    } else {
        for (int e = e0; e < E; e++) {
            int s = esrc[e], d = edst[e];
            float4 v = __ldg(mp + (size_t)s * 8 + j);
            float x = fmaf(v.x, scx, shx), y = fmaf(v.y, scy, shy);
            float z = fmaf(v.z, scz, shz), w = fmaf(v.w, scw, shw);
            float* p = g_agg + (size_t)d * 32 + c0;
            asm volatile("red.global.add.v4.f32 [%0], {%1,%2,%3,%4};" :: "l"(p), "f"(x), "f"(y), "f"(z), "f"(w) : "memory");
        }
    }
}

// ================= K4: u_raw = ReLU([agg, BN(h), goal] @ W_upd + b) ================
// tile 64 nodes; warp = 8 nodes (4 pairs) x 64 ch
__global__ __launch_bounds__(256) void k4_update(
    const float* __restrict__ goal, const float* __restrict__ Wu,
    const float* __restrict__ bu, const float* __restrict__ gam,
    const float* __restrict__ bet, int Nn, float invN)
{
    __shared__ float sWt[112 * 64];        // 28 KB folded [k][c]
    __shared__ ulonglong2 sC[32 * 57];     // 29.2 KB
    __shared__ float sSc[64], sSh[64], sB[64];
    __shared__ float rs[64], rq[64];
    int tid = threadIdx.x;
    if (tid < 64) {
        float mean = g_stats[tid] * invN;
        float var  = fmaf(-mean, mean, g_stats[64 + tid] * invN);
        float r = rsqrtf(var + EPS);
        float s = gam[tid] * r;
        sSc[tid] = s; sSh[tid] = bet[tid] - mean * s;
        sB[tid] = bu[tid]; rs[tid] = 0.f; rq[tid] = 0.f;
    }
    __syncthreads();
    for (int i = tid; i < 112 * 64; i += 256) {
        int k = i >> 6;
        float f = (k >= 32 && k < 96) ? sSc[k - 32] : 1.f;
        sWt[i] = Wu[i] * f;
    }
    {
        int cc = tid & 63, part = tid >> 6;
        float acc = 0.f;
        #pragma unroll
        for (int j = part * 16; j < part * 16 + 16; j++) acc += sSh[j] * Wu[(32 + j) * 64 + cc];
        atomicAdd(&sB[cc], acc);
    }
    __syncthreads();
    int c = tid & 31, wp = tid >> 5;
    ull bl = dup2(sB[c]), bh = dup2(sB[c + 32]);
    float s0 = 0.f, q0 = 0.f, s1 = 0.f, q1 = 0.f;
    float* sCf = (float*)sC;
    const float4* ap = (const float4*)g_agg;
    const float4* hp = (const float4*)g_buf_h;
    const float4* gp = (const float4*)goal;
    float4 z4 = make_float4(0.f, 0.f, 0.f, 0.f);

    for (int tile = blockIdx.x * 64; tile < Nn; tile += gridDim.x * 64) {
        __syncthreads();
        for (int f = tid; f < 1792; f += 256) {
            int n, k0;
            float4 v;
            if (f < 512) {
                n = f >> 3; int j = f & 7; k0 = j * 4;
                int gn = tile + n;
                v = (gn < Nn) ? ap[(size_t)gn * 8 + j] : z4;
            } else if (f < 1536) {
                int gnd = f - 512;
                n = gnd >> 4; int j = gnd & 15; k0 = 32 + j * 4;
                int gn = tile + n;
                v = (gn < Nn) ? hp[(size_t)gn * 16 + j] : z4;
            } else {
                int gnd = f - 1536;
                n = gnd >> 2; int j = gnd & 3; k0 = 96 + j * 4;
                int gn = tile + n;
                v = (gn < Nn) ? gp[(size_t)gn * 4 + j] : z4;
            }
            float* dst = sCf + (n >> 1) * 228 + (n & 1);
            dst[(k0 + 0) * 2] = v.x; dst[(k0 + 1) * 2] = v.y;
            dst[(k0 + 2) * 2] = v.z; dst[(k0 + 3) * 2] = v.w;
        }
        __syncthreads();

        ull a0[4], a1[4];
        #pragma unroll
        for (int p = 0; p < 4; p++) { a0[p] = bl; a1[p] = bh; }
        #pragma unroll 4
        for (int k2 = 0; k2 < 56; k2++) {
            int k = k2 * 2;
            ull w0 = dup2(sWt[k * 64 + c]),        w1 = dup2(sWt[k * 64 + c + 32]);
            ull w2 = dup2(sWt[(k + 1) * 64 + c]),  w3 = dup2(sWt[(k + 1) * 64 + c + 32]);
            #pragma unroll
            for (int p = 0; p < 4; p++) {
                ulonglong2 x = sC[(wp * 4 + p) * 57 + k2];
                ffma2(a0[p], x.x, w0); ffma2(a1[p], x.x, w1);
                ffma2(a0[p], x.y, w2); ffma2(a1[p], x.y, w3);
            }
        }
        #pragma unroll
        for (int p = 0; p < 4; p++) {
            float2 f0 = unp2(a0[p]), f1 = unp2(a1[p]);
            int n0 = tile + wp * 8 + 2 * p;
            float v;
            if (n0 < Nn) {
                v = fmaxf(f0.x, 0.f); g_buf_u[(size_t)n0 * 64 + c] = v;        s0 += v; q0 += v * v;
                v = fmaxf(f1.x, 0.f); g_buf_u[(size_t)n0 * 64 + c + 32] = v;   s1 += v; q1 += v * v;
            }
            if (n0 + 1 < Nn) {
                v = fmaxf(f0.y, 0.f); g_buf_u[(size_t)(n0 + 1) * 64 + c] = v;      s0 += v; q0 += v * v;
                v = fmaxf(f1.y, 0.f); g_buf_u[(size_t)(n0 + 1) * 64 + c + 32] = v; s1 += v; q1 += v * v;
            }
        }
    }
    __syncthreads();
    atomicAdd(&rs[c], s0);      atomicAdd(&rq[c], q0);
    atomicAdd(&rs[c + 32], s1); atomicAdd(&rq[c + 32], q1);
    __syncthreads();
    if (tid < 64) { atomicAdd(&g_stats[256 + tid], rs[tid]); atomicAdd(&g_stats[320 + tid], rq[tid]); }
}

// ================= K5: u = BN(u_raw); out = u @ W_out + b_out ======================
// tile 32 nodes; all 8 warps do the GEMM (lane = node(4) x oc(8))
__global__ __launch_bounds__(256) void k5_output(
    const float* __restrict__ Wo, const float* __restrict__ bo,
    const float* __restrict__ gam, const float* __restrict__ bet,
    float* __restrict__ out_u, float* __restrict__ out_o,
    int Nn, float invN)
{
    __shared__ float sWt[8 * 64];          // [oc][k]
    __shared__ float sU[32 * 68];          // padded, 16B aligned rows
    __shared__ float sScale[64], sShift[64];
    int tid = threadIdx.x;
    for (int i = tid; i < 512; i += 256) {
        int k = i >> 3, oc = i & 7;
        sWt[oc * 64 + k] = Wo[i];
    }
    if (tid < 64) {
        float mean = g_stats[256 + tid] * invN;
        float var  = fmaf(-mean, mean, g_stats[320 + tid] * invN);
        float r    = rsqrtf(var + EPS);
        float sc   = gam[tid] * r;
        sScale[tid] = sc; sShift[tid] = bet[tid] - mean * sc;
    }
    int lane = tid & 31, wp = tid >> 5;
    float bias = bo[lane & 7];
    int ln = wp * 4 + (lane >> 3);         // local node 0..31
    int oc = lane & 7;

    for (int tile = blockIdx.x * 32; tile < Nn; tile += gridDim.x * 32) {
        __syncthreads();
        for (int i = tid; i < 2048; i += 256) {
            int n = i >> 6, cc = i & 63;
            int gn = tile + n;
            float u = 0.f;
            if (gn < Nn) {
                u = fmaf(g_buf_u[(size_t)gn * 64 + cc], sScale[cc], sShift[cc]);
                out_u[(size_t)gn * 64 + cc] = u;
            }
            sU[n * 68 + cc] = u;
        }
        __syncthreads();
        int gn = tile + ln;
        if (gn < Nn) {
            float acc = bias;
            #pragma unroll
            for (int kk = 0; kk < 16; kk++) {
                float4 uv = *reinterpret_cast<const float4*>(&sU[ln * 68 + kk * 4]);
                float4 wv = *reinterpret_cast<const float4*>(&sWt[oc * 64 + kk * 4]);
                acc = fmaf(uv.x, wv.x, acc); acc = fmaf(uv.y, wv.y, acc);
                acc = fmaf(uv.z, wv.z, acc); acc = fmaf(uv.w, wv.w, acc);
            }
            out_o[(size_t)gn * 8 + oc] = acc;
        }
    }
}

// ---------------- host launcher ----------------
extern "C" void kernel_launch(void* const* d_in, const int* in_sizes, int n_in,
                              void* d_out, int out_size)
{
    const float* nodes  = (const float*)d_in[0];
    const float* goal   = (const float*)d_in[1];
    const int*   esrc   = (const int*)d_in[2];
    const int*   edst   = (const int*)d_in[3];
    const float* W_in   = (const float*)d_in[6];
    const float* b_in   = (const float*)d_in[7];
    const float* g_in   = (const float*)d_in[8];
    const float* be_in  = (const float*)d_in[9];
    const float* W_msg  = (const float*)d_in[10];
    const float* b_msg  = (const float*)d_in[11];
    const float* g_msg  = (const float*)d_in[12];
    const float* be_msg = (const float*)d_in[13];
    const float* W_upd  = (const float*)d_in[14];
    const float* b_upd  = (const float*)d_in[15];
    const float* g_upd  = (const float*)d_in[16];
    const float* be_upd = (const float*)d_in[17];
    const float* W_out  = (const float*)d_in[18];
    const float* b_out  = (const float*)d_in[19];

    int N = in_sizes[0] / 32;
    int E = in_sizes[2];
    float invN = 1.0f / (float)N;

    float* dout = (float*)d_out;
    float* out_u;
    float* out_o;
    if ((long long)out_size >= (long long)N * 72) {
        out_u = dout;
        out_o = dout + (size_t)N * 64;
    } else if ((long long)out_size == (long long)N * 8) {
        void* p; cudaGetSymbolAddress(&p, g_buf_m);
        out_u = (float*)p;  out_o = dout;
    } else {
        void* p; cudaGetSymbolAddress(&p, g_buf_m);
        out_u = dout;       out_o = (float*)p;
    }

    // reset stats via memset node (graph-capturable)
    void* statsPtr; cudaGetSymbolAddress(&statsPtr, g_stats);
    cudaMemsetAsync(statsPtr, 0, 384 * sizeof(float));

    int tiles128 = (N + 127) / 128;
    k1_input<<<tiles128, 256>>>(nodes, W_in, b_in, N, N * 8);
    k2_msg  <<<tiles128, 256>>>(W_msg, b_msg, g_in, be_in, N, invN);
    long long groups = ((long long)E + 3) / 4;
    long long thr = groups * 8;
    k3_edges<<<(int)((thr + 255) / 256), 256>>>(esrc, edst, g_msg, be_msg, E, invN);
    k4_update<<<444, 256>>>(goal, W_upd, b_upd, g_in, be_in, N, invN);
    k5_output<<<640, 256>>>(W_out, b_out, g_upd, be_upd, out_u, out_o, N, invN);
}